// round 1
// baseline (speedup 1.0000x reference)
#include <cuda_runtime.h>

// ---------------------------------------------------------------------------
// MambaSSM: B=2, L=384, d_inner=384, d_state=384, dt_rank=384, d_conv=4
//
// Pipeline:
//   GEMM1 (fused): dt = softplus(x @ dt_w^T + dt_b)   -> g_DT   [768x384]
//                  x_dbl = x @ B_w^T                  -> g_XDBL [768x384]
//   K3:            u = silu(causal_conv(x)+cb); pack per-channel scalar stream
//                  g_SC[b][d][l] = (dt, dt*u, u*D[d], 0)
//   GEMM2 (fused): Bm = x_dbl @ B_w^T                 -> g_BM   [768x384]
//                  Cm = x_dbl @ C_w^T                 -> g_CM   [768x384]
//   SCAN: per channel (b,d):  h[s] <- exp(dt_l*A[d,s])*h[s] + (dt_l*u_l)*Bm[b,d,s]
//         y[b,l,d] = sum_s h[s]*Cm[b,l,s] + u_l*D[d]
//   (quirky reference broadcast: Bm's "L" index is the channel index d)
// ---------------------------------------------------------------------------

#define LOG2E 1.4426950408889634f

__device__ float  g_DT  [768 * 384];
__device__ float  g_XDBL[768 * 384];
__device__ float  g_BM  [768 * 384];
__device__ float  g_CM  [768 * 384];
__device__ float4 g_SC  [768 * 384];   // [b][d][l] : (dt, dt*u, u*D, 0)

__device__ __forceinline__ float ex2f(float x) {
    float y;
    asm("ex2.approx.ftz.f32 %0, %1;" : "=f"(y) : "f"(x));
    return y;
}

// ---------------------------------------------------------------------------
// Dual-output tiled SGEMM: C[m,n] = sum_k A[m,k] * W[n,k]   (row-row dot)
// M=768, K=384, N=2x384 (two weight matrices, two outputs).
// phase 0: A=x,      Wa=dt_w (bias+softplus -> g_DT), Wb=B_w (-> g_XDBL)
// phase 1: A=g_XDBL, Wa=B_w  (-> g_BM),               Wb=C_w (-> g_CM)
// Tile 64x64, BK=16, 256 threads, 4x4 per-thread microtile, reg-prefetch.
// ---------------------------------------------------------------------------
__global__ __launch_bounds__(256) void gemm_dual(
    const float* __restrict__ A_ext,
    const float* __restrict__ Wa,
    const float* __restrict__ Wb,
    const float* __restrict__ bias,
    int phase)
{
    __shared__ float As[16][64];
    __shared__ float Bs[16][64];

    const float* A  = (phase == 0) ? A_ext : g_XDBL;
    float*       Ca = (phase == 0) ? g_DT  : g_BM;
    float*       Cb = (phase == 0) ? g_XDBL: g_CM;

    const int tid = threadIdx.x;
    const int m0  = blockIdx.x * 64;
    const int bn  = blockIdx.y;            // 0..11
    const bool second = (bn >= 6);
    const float* W  = second ? Wb : Wa;
    float*       Cc = second ? Cb : Ca;
    const bool doAct = (phase == 0) && !second;
    const int n0 = (second ? bn - 6 : bn) * 64;

    const int loadRow = tid >> 2;          // 0..63
    const int loadCol = (tid & 3) << 2;    // 0,4,8,12
    const float* Ap = A + (m0 + loadRow) * 384 + loadCol;
    const float* Wp = W + (n0 + loadRow) * 384 + loadCol;

    float4 aR = *(const float4*)Ap;
    float4 wR = *(const float4*)Wp;

    float acc[4][4];
#pragma unroll
    for (int i = 0; i < 4; i++)
#pragma unroll
        for (int j = 0; j < 4; j++) acc[i][j] = 0.f;

    const int tx = tid & 15;
    const int ty = tid >> 4;

    for (int kt = 0; kt < 24; ++kt) {
        As[loadCol + 0][loadRow] = aR.x;
        As[loadCol + 1][loadRow] = aR.y;
        As[loadCol + 2][loadRow] = aR.z;
        As[loadCol + 3][loadRow] = aR.w;
        Bs[loadCol + 0][loadRow] = wR.x;
        Bs[loadCol + 1][loadRow] = wR.y;
        Bs[loadCol + 2][loadRow] = wR.z;
        Bs[loadCol + 3][loadRow] = wR.w;
        __syncthreads();

        if (kt < 23) {  // prefetch next K-tile into registers
            aR = *(const float4*)(Ap + (kt + 1) * 16);
            wR = *(const float4*)(Wp + (kt + 1) * 16);
        }

#pragma unroll
        for (int k = 0; k < 16; ++k) {
            float4 av = *(const float4*)&As[k][ty << 2];
            float4 bv = *(const float4*)&Bs[k][tx << 2];
            float a[4] = {av.x, av.y, av.z, av.w};
            float b[4] = {bv.x, bv.y, bv.z, bv.w};
#pragma unroll
            for (int i = 0; i < 4; i++)
#pragma unroll
                for (int j = 0; j < 4; j++)
                    acc[i][j] = fmaf(a[i], b[j], acc[i][j]);
        }
        __syncthreads();
    }

#pragma unroll
    for (int i = 0; i < 4; i++) {
        const int m = m0 + (ty << 2) + i;
#pragma unroll
        for (int j = 0; j < 4; j++) {
            const int n = n0 + (tx << 2) + j;
            float v = acc[i][j];
            if (doAct) {  // softplus(v + bias) (stable)
                v += bias[n];
                v = fmaxf(v, 0.f) + log1pf(expf(-fabsf(v)));
            }
            Cc[m * 384 + n] = v;
        }
    }
}

// ---------------------------------------------------------------------------
// K3: causal depthwise conv(4) + silu, pack scalar stream g_SC[b][d][l].
// grid (24, 2), block 384 (thread = channel d), 16 l's per block.
// ---------------------------------------------------------------------------
__global__ __launch_bounds__(384) void conv_sc_kernel(
    const float* __restrict__ x,
    const float* __restrict__ convw,
    const float* __restrict__ convb,
    const float* __restrict__ Dvec)
{
    const int d  = threadIdx.x;
    const int b  = blockIdx.y;
    const int l0 = blockIdx.x * 16;

    const float c0 = convw[d * 4 + 0];
    const float c1 = convw[d * 4 + 1];
    const float c2 = convw[d * 4 + 2];
    const float c3 = convw[d * 4 + 3];
    const float cb = convb[d];
    const float Dd = Dvec[d];

    const float* xb  = x    + b * 384 * 384 + d;
    const float* dtp = g_DT + b * 384 * 384 + d;
    float4*      scp = g_SC + (b * 384 + d) * 384;

    float w0 = (l0 - 3 >= 0) ? xb[(l0 - 3) * 384] : 0.f;
    float w1 = (l0 - 2 >= 0) ? xb[(l0 - 2) * 384] : 0.f;
    float w2 = (l0 - 1 >= 0) ? xb[(l0 - 1) * 384] : 0.f;

    for (int i = 0; i < 16; ++i) {
        const int l = l0 + i;
        const float w3 = xb[l * 384];
        float v = fmaf(w0, c0, fmaf(w1, c1, fmaf(w2, c2, fmaf(w3, c3, cb))));
        const float u  = v / (1.f + expf(-v));     // silu
        const float dt = dtp[l * 384];
        scp[l] = make_float4(dt, dt * u, u * Dd, 0.f);
        w0 = w1; w1 = w2; w2 = w3;
    }
}

// ---------------------------------------------------------------------------
// SCAN: one warp per channel (b,d). 384 states split 12/lane as 3x float4
// (s = (lane + 32*j)*4 + comp). 4 channels per CTA share b -> L1 reuse of Cm.
// ---------------------------------------------------------------------------
__global__ __launch_bounds__(128) void scan_kernel(
    const float* __restrict__ A_log,
    float* __restrict__ out)
{
    const int wid  = threadIdx.x >> 5;
    const int lane = threadIdx.x & 31;
    const int w = blockIdx.x * 4 + wid;     // 0..767
    const int b = w / 384;
    const int d = w - b * 384;

    const float4* Arow = (const float4*)(A_log + d * 384);
    const float4* Brow = (const float4*)(g_BM + (b * 384 + d) * 384);

    float4 A2[3], Bm[3], h[3];
#pragma unroll
    for (int j = 0; j < 3; ++j) {
        float4 a = Arow[lane + 32 * j];
        A2[j].x = -expf(a.x) * LOG2E;
        A2[j].y = -expf(a.y) * LOG2E;
        A2[j].z = -expf(a.z) * LOG2E;
        A2[j].w = -expf(a.w) * LOG2E;
        Bm[j] = Brow[lane + 32 * j];
        h[j]  = make_float4(0.f, 0.f, 0.f, 0.f);
    }

    const float4* Cb  = (const float4*)(g_CM + b * 384 * 384);
    const float4* scp = g_SC + (b * 384 + d) * 384;
    float* outp = out + (size_t)b * 384 * 384 + d;

#define UPD(hf, af, bf, cf, accv)                          \
    {                                                      \
        float e_ = ex2f(a_dt * (af));                      \
        (hf) = fmaf(e_, (hf), c_dt * (bf));                \
        (accv) = fmaf((hf), (cf), (accv));                 \
    }

#pragma unroll 2
    for (int l = 0; l < 384; ++l) {
        const float4 sc = scp[l];                 // uniform per warp (L1 hit)
        const float a_dt = sc.x;
        const float c_dt = sc.y;
        const float4* Crow = Cb + l * 96;
        const float4 C0 = Crow[lane];
        const float4 C1 = Crow[lane + 32];
        const float4 C2 = Crow[lane + 64];

        float acc0 = 0.f, acc1 = 0.f, acc2 = 0.f;
        UPD(h[0].x, A2[0].x, Bm[0].x, C0.x, acc0);
        UPD(h[0].y, A2[0].y, Bm[0].y, C0.y, acc0);
        UPD(h[0].z, A2[0].z, Bm[0].z, C0.z, acc0);
        UPD(h[0].w, A2[0].w, Bm[0].w, C0.w, acc0);
        UPD(h[1].x, A2[1].x, Bm[1].x, C1.x, acc1);
        UPD(h[1].y, A2[1].y, Bm[1].y, C1.y, acc1);
        UPD(h[1].z, A2[1].z, Bm[1].z, C1.z, acc1);
        UPD(h[1].w, A2[1].w, Bm[1].w, C1.w, acc1);
        UPD(h[2].x, A2[2].x, Bm[2].x, C2.x, acc2);
        UPD(h[2].y, A2[2].y, Bm[2].y, C2.y, acc2);
        UPD(h[2].z, A2[2].z, Bm[2].z, C2.z, acc2);
        UPD(h[2].w, A2[2].w, Bm[2].w, C2.w, acc2);

        float s = (acc0 + acc1) + acc2;
        s += __shfl_xor_sync(0xffffffffu, s, 16);
        s += __shfl_xor_sync(0xffffffffu, s, 8);
        s += __shfl_xor_sync(0xffffffffu, s, 4);
        s += __shfl_xor_sync(0xffffffffu, s, 2);
        s += __shfl_xor_sync(0xffffffffu, s, 1);
        if (lane == 0) outp[l * 384] = s + sc.z;
    }
#undef UPD
}

// ---------------------------------------------------------------------------
extern "C" void kernel_launch(void* const* d_in, const int* in_sizes, int n_in,
                              void* d_out, int out_size)
{
    const float* x      = (const float*)d_in[0];
    const float* A_log  = (const float*)d_in[1];
    const float* Dvec   = (const float*)d_in[2];
    const float* dt_w   = (const float*)d_in[3];
    const float* dt_b   = (const float*)d_in[4];
    const float* B_w    = (const float*)d_in[5];
    const float* C_w    = (const float*)d_in[6];
    const float* conv_w = (const float*)d_in[7];
    const float* conv_b = (const float*)d_in[8];
    float* out = (float*)d_out;

    // GEMM1: dt (softplus) + x_dbl
    gemm_dual<<<dim3(12, 12), 256>>>(x, dt_w, B_w, dt_b, 0);
    // K3: conv + silu + scalar pack (depends on g_DT)
    conv_sc_kernel<<<dim3(24, 2), 384>>>(x, conv_w, conv_b, Dvec);
    // GEMM2: Bm + Cm (depends on g_XDBL)
    gemm_dual<<<dim3(12, 12), 256>>>(x, B_w, C_w, nullptr, 1);
    // Scan
    scan_kernel<<<192, 128>>>(A_log, out);
}

// round 2
// speedup vs baseline: 1.2815x; 1.2815x over previous
#include <cuda_runtime.h>

// ---------------------------------------------------------------------------
// MambaSSM: B=2, L=384, d_inner=384, d_state=384, dt_rank=384, d_conv=4
//
//   GEMM1 (fused): dt = softplus(x @ dt_w^T + dt_b)   -> g_DT   [768x384]
//                  x_dbl = x @ B_w^T                  -> g_XDBL [768x384]
//   K3:            u = silu(causal_conv(x)+cb); pack per-channel scalar stream
//                  g_SC[b][d][l] = (dt, dt*u, u*D[d], 0)
//   GEMM2 (fused): Bm = x_dbl @ B_w^T                 -> g_BM   [768x384]
//                  Cm = x_dbl @ C_w^T                 -> g_CM   [768x384]
//   SCAN: per channel (b,d):  h[s] <- exp(dt_l*A[d,s])*h[s] + (dt_l*u_l)*Bm[b,d,s]
//         y[b,l,d] = sum_s h[s]*Cm[b,l,s] + u_l*D[d]
//
// Scan v2: CTA = 2 channels (same b), 6 warps, 2 states/lane (float2).
//   - warps independent over l (no per-step sync); per-l warp partials go to
//     smem rows; single final reduction pass.
//   - C row loads shared by both channels (halves L2 traffic).
//   - sc + C prefetched one step ahead.
// ---------------------------------------------------------------------------

#define LOG2E 1.4426950408889634f

__device__ float  g_DT  [768 * 384];
__device__ float  g_XDBL[768 * 384];
__device__ float  g_BM  [768 * 384];
__device__ float  g_CM  [768 * 384];
__device__ float4 g_SC  [768 * 384];   // [b][d][l] : (dt, dt*u, u*D, 0)

__device__ __forceinline__ float ex2f(float x) {
    float y;
    asm("ex2.approx.ftz.f32 %0, %1;" : "=f"(y) : "f"(x));
    return y;
}

// ---------------------------------------------------------------------------
// Dual-output tiled SGEMM: C[m,n] = sum_k A[m,k] * W[n,k]
// phase 0: A=x,      Wa=dt_w (bias+softplus -> g_DT), Wb=B_w (-> g_XDBL)
// phase 1: A=g_XDBL, Wa=B_w  (-> g_BM),               Wb=C_w (-> g_CM)
// ---------------------------------------------------------------------------
__global__ __launch_bounds__(256) void gemm_dual(
    const float* __restrict__ A_ext,
    const float* __restrict__ Wa,
    const float* __restrict__ Wb,
    const float* __restrict__ bias,
    int phase)
{
    __shared__ float As[16][64];
    __shared__ float Bs[16][64];

    const float* A  = (phase == 0) ? A_ext : g_XDBL;
    float*       Ca = (phase == 0) ? g_DT  : g_BM;
    float*       Cb = (phase == 0) ? g_XDBL: g_CM;

    const int tid = threadIdx.x;
    const int m0  = blockIdx.x * 64;
    const int bn  = blockIdx.y;            // 0..11
    const bool second = (bn >= 6);
    const float* W  = second ? Wb : Wa;
    float*       Cc = second ? Cb : Ca;
    const bool doAct = (phase == 0) && !second;
    const int n0 = (second ? bn - 6 : bn) * 64;

    const int loadRow = tid >> 2;          // 0..63
    const int loadCol = (tid & 3) << 2;    // 0,4,8,12
    const float* Ap = A + (m0 + loadRow) * 384 + loadCol;
    const float* Wp = W + (n0 + loadRow) * 384 + loadCol;

    float4 aR = *(const float4*)Ap;
    float4 wR = *(const float4*)Wp;

    float acc[4][4];
#pragma unroll
    for (int i = 0; i < 4; i++)
#pragma unroll
        for (int j = 0; j < 4; j++) acc[i][j] = 0.f;

    const int tx = tid & 15;
    const int ty = tid >> 4;

    for (int kt = 0; kt < 24; ++kt) {
        As[loadCol + 0][loadRow] = aR.x;
        As[loadCol + 1][loadRow] = aR.y;
        As[loadCol + 2][loadRow] = aR.z;
        As[loadCol + 3][loadRow] = aR.w;
        Bs[loadCol + 0][loadRow] = wR.x;
        Bs[loadCol + 1][loadRow] = wR.y;
        Bs[loadCol + 2][loadRow] = wR.z;
        Bs[loadCol + 3][loadRow] = wR.w;
        __syncthreads();

        if (kt < 23) {
            aR = *(const float4*)(Ap + (kt + 1) * 16);
            wR = *(const float4*)(Wp + (kt + 1) * 16);
        }

#pragma unroll
        for (int k = 0; k < 16; ++k) {
            float4 av = *(const float4*)&As[k][ty << 2];
            float4 bv = *(const float4*)&Bs[k][tx << 2];
            float a[4] = {av.x, av.y, av.z, av.w};
            float b[4] = {bv.x, bv.y, bv.z, bv.w};
#pragma unroll
            for (int i = 0; i < 4; i++)
#pragma unroll
                for (int j = 0; j < 4; j++)
                    acc[i][j] = fmaf(a[i], b[j], acc[i][j]);
        }
        __syncthreads();
    }

#pragma unroll
    for (int i = 0; i < 4; i++) {
        const int m = m0 + (ty << 2) + i;
#pragma unroll
        for (int j = 0; j < 4; j++) {
            const int n = n0 + (tx << 2) + j;
            float v = acc[i][j];
            if (doAct) {
                v += bias[n];
                v = fmaxf(v, 0.f) + log1pf(expf(-fabsf(v)));
            }
            Cc[m * 384 + n] = v;
        }
    }
}

// ---------------------------------------------------------------------------
// K3: causal depthwise conv(4) + silu, pack scalar stream g_SC[b][d][l].
// ---------------------------------------------------------------------------
__global__ __launch_bounds__(384) void conv_sc_kernel(
    const float* __restrict__ x,
    const float* __restrict__ convw,
    const float* __restrict__ convb,
    const float* __restrict__ Dvec)
{
    const int d  = threadIdx.x;
    const int b  = blockIdx.y;
    const int l0 = blockIdx.x * 16;

    const float c0 = convw[d * 4 + 0];
    const float c1 = convw[d * 4 + 1];
    const float c2 = convw[d * 4 + 2];
    const float c3 = convw[d * 4 + 3];
    const float cb = convb[d];
    const float Dd = Dvec[d];

    const float* xb  = x    + b * 384 * 384 + d;
    const float* dtp = g_DT + b * 384 * 384 + d;
    float4*      scp = g_SC + (b * 384 + d) * 384;

    float w0 = (l0 - 3 >= 0) ? xb[(l0 - 3) * 384] : 0.f;
    float w1 = (l0 - 2 >= 0) ? xb[(l0 - 2) * 384] : 0.f;
    float w2 = (l0 - 1 >= 0) ? xb[(l0 - 1) * 384] : 0.f;

    for (int i = 0; i < 16; ++i) {
        const int l = l0 + i;
        const float w3 = xb[l * 384];
        float v = fmaf(w0, c0, fmaf(w1, c1, fmaf(w2, c2, fmaf(w3, c3, cb))));
        const float u  = v / (1.f + expf(-v));     // silu
        const float dt = dtp[l * 384];
        scp[l] = make_float4(dt, dt * u, u * Dd, 0.f);
        w0 = w1; w1 = w2; w2 = w3;
    }
}

// ---------------------------------------------------------------------------
// SCAN v2: grid 384 CTAs, 192 threads (6 warps). CTA handles channels
// (b, d0) and (b, d0+1). Warp w, lane: float2 state index s2 = w*32+lane.
// Warps never sync inside the l-loop; per-l warp partials go to smem.
// ---------------------------------------------------------------------------
__global__ __launch_bounds__(192) void scan_kernel(
    const float* __restrict__ A_log,
    float* __restrict__ out)
{
    __shared__ float part[2][6][384];

    const int wid  = threadIdx.x >> 5;      // 0..5
    const int lane = threadIdx.x & 31;
    const int s2   = wid * 32 + lane;       // float2 index 0..191

    const int pid = blockIdx.x;             // 0..383
    const int b   = pid / 192;
    const int d0  = (pid - b * 192) * 2;
    const int d1  = d0 + 1;

    // Per-channel invariants
    const float2 a0 = ((const float2*)(A_log + d0 * 384))[s2];
    const float2 a1 = ((const float2*)(A_log + d1 * 384))[s2];
    const float A0x = -expf(a0.x) * LOG2E, A0y = -expf(a0.y) * LOG2E;
    const float A1x = -expf(a1.x) * LOG2E, A1y = -expf(a1.y) * LOG2E;
    const float2 Bm0 = ((const float2*)(g_BM + (b * 384 + d0) * 384))[s2];
    const float2 Bm1 = ((const float2*)(g_BM + (b * 384 + d1) * 384))[s2];

    float h0x = 0.f, h0y = 0.f, h1x = 0.f, h1y = 0.f;

    const float4* scp0 = g_SC + (b * 384 + d0) * 384;
    const float4* scp1 = g_SC + (b * 384 + d1) * 384;
    const float2* Cb2  = (const float2*)(g_CM + b * 147456);

    // prefetch l=0
    float4 sA = scp0[0];
    float4 sB = scp1[0];
    float2 Cn = Cb2[s2];

#pragma unroll 2
    for (int l = 0; l < 384; ++l) {
        const float4 s0 = sA;
        const float4 s1 = sB;
        const float2 Cv = Cn;
        const int ln = (l < 383) ? (l + 1) : 383;
        sA = scp0[ln];
        sB = scp1[ln];
        Cn = Cb2[ln * 192 + s2];

        float e, acc0, acc1;
        e = ex2f(s0.x * A0x); h0x = fmaf(e, h0x, s0.y * Bm0.x); acc0 = h0x * Cv.x;
        e = ex2f(s0.x * A0y); h0y = fmaf(e, h0y, s0.y * Bm0.y); acc0 = fmaf(h0y, Cv.y, acc0);
        e = ex2f(s1.x * A1x); h1x = fmaf(e, h1x, s1.y * Bm1.x); acc1 = h1x * Cv.x;
        e = ex2f(s1.x * A1y); h1y = fmaf(e, h1y, s1.y * Bm1.y); acc1 = fmaf(h1y, Cv.y, acc1);

#pragma unroll
        for (int off = 16; off > 0; off >>= 1) {
            acc0 += __shfl_xor_sync(0xffffffffu, acc0, off);
            acc1 += __shfl_xor_sync(0xffffffffu, acc1, off);
        }
        if (lane == 0) {
            part[0][wid][l] = acc0;
            part[1][wid][l] = acc1;
        }
    }

    __syncthreads();

    // Final reduce: y[l] = sum over 6 warps + u*D
    for (int l = threadIdx.x; l < 384; l += 192) {
        float y0 = ((part[0][0][l] + part[0][1][l]) + (part[0][2][l] + part[0][3][l]))
                 + (part[0][4][l] + part[0][5][l]);
        float y1 = ((part[1][0][l] + part[1][1][l]) + (part[1][2][l] + part[1][3][l]))
                 + (part[1][4][l] + part[1][5][l]);
        y0 += scp0[l].z;
        y1 += scp1[l].z;
        float* op = out + (size_t)b * 147456 + (size_t)l * 384;
        op[d0] = y0;
        op[d1] = y1;
    }
}

// ---------------------------------------------------------------------------
extern "C" void kernel_launch(void* const* d_in, const int* in_sizes, int n_in,
                              void* d_out, int out_size)
{
    const float* x      = (const float*)d_in[0];
    const float* A_log  = (const float*)d_in[1];
    const float* Dvec   = (const float*)d_in[2];
    const float* dt_w   = (const float*)d_in[3];
    const float* dt_b   = (const float*)d_in[4];
    const float* B_w    = (const float*)d_in[5];
    const float* C_w    = (const float*)d_in[6];
    const float* conv_w = (const float*)d_in[7];
    const float* conv_b = (const float*)d_in[8];
    float* out = (float*)d_out;

    gemm_dual<<<dim3(12, 12), 256>>>(x, dt_w, B_w, dt_b, 0);
    conv_sc_kernel<<<dim3(24, 2), 384>>>(x, conv_w, conv_b, Dvec);
    gemm_dual<<<dim3(12, 12), 256>>>(x, B_w, C_w, nullptr, 1);
    scan_kernel<<<384, 192>>>(A_log, out);
}

// round 3
// speedup vs baseline: 1.4034x; 1.0951x over previous
#include <cuda_runtime.h>

// ---------------------------------------------------------------------------
// MambaSSM: B=2, L=384, d_inner=384, d_state=384, dt_rank=384, d_conv=4
//
//   GEMM1 (fused): dt = softplus(x @ dt_w^T + dt_b)   -> g_DT   [768x384]
//                  x_dbl = x @ B_w^T                  -> g_XDBL [768x384]
//   K3:            u = silu(causal_conv(x)+cb); pack per-channel scalar stream
//                  g_SC[b][d][l] = (dt, dt*u, u*D[d], 0)
//   GEMM2 (fused): Bm = x_dbl @ B_w^T                 -> g_BM   [768x384]
//                  Cm = x_dbl @ C_w^T                 -> g_CM   [768x384]
//   SCAN v3: CTA = 4 channels (same b), 192 threads (6 warps).
//     lane owns float2 of state dim (s2 = tid, 0..191) for all 4 channels
//     -> 8 independent scalar recurrences per lane (deep ILP, no long chains).
//     Per step: 2-level shuffle (32->8) per channel, lanes<8 STS.128 the 4
//     channel partials. Every 48 steps: one smem tree-reduce + output write.
// ---------------------------------------------------------------------------

#define LOG2E 1.4426950408889634f

__device__ float  g_DT  [768 * 384];
__device__ float  g_XDBL[768 * 384];
__device__ float  g_BM  [768 * 384];
__device__ float  g_CM  [768 * 384];
__device__ float4 g_SC  [768 * 384];   // [b][d][l] : (dt, dt*u, u*D, 0)

__device__ __forceinline__ float ex2f(float x) {
    float y;
    asm("ex2.approx.ftz.f32 %0, %1;" : "=f"(y) : "f"(x));
    return y;
}

// ---------------------------------------------------------------------------
// Dual-output tiled SGEMM: C[m,n] = sum_k A[m,k] * W[n,k]
// ---------------------------------------------------------------------------
__global__ __launch_bounds__(256) void gemm_dual(
    const float* __restrict__ A_ext,
    const float* __restrict__ Wa,
    const float* __restrict__ Wb,
    const float* __restrict__ bias,
    int phase)
{
    __shared__ float As[16][64];
    __shared__ float Bs[16][64];

    const float* A  = (phase == 0) ? A_ext : g_XDBL;
    float*       Ca = (phase == 0) ? g_DT  : g_BM;
    float*       Cb = (phase == 0) ? g_XDBL: g_CM;

    const int tid = threadIdx.x;
    const int m0  = blockIdx.x * 64;
    const int bn  = blockIdx.y;            // 0..11
    const bool second = (bn >= 6);
    const float* W  = second ? Wb : Wa;
    float*       Cc = second ? Cb : Ca;
    const bool doAct = (phase == 0) && !second;
    const int n0 = (second ? bn - 6 : bn) * 64;

    const int loadRow = tid >> 2;          // 0..63
    const int loadCol = (tid & 3) << 2;    // 0,4,8,12
    const float* Ap = A + (m0 + loadRow) * 384 + loadCol;
    const float* Wp = W + (n0 + loadRow) * 384 + loadCol;

    float4 aR = *(const float4*)Ap;
    float4 wR = *(const float4*)Wp;

    float acc[4][4];
#pragma unroll
    for (int i = 0; i < 4; i++)
#pragma unroll
        for (int j = 0; j < 4; j++) acc[i][j] = 0.f;

    const int tx = tid & 15;
    const int ty = tid >> 4;

    for (int kt = 0; kt < 24; ++kt) {
        As[loadCol + 0][loadRow] = aR.x;
        As[loadCol + 1][loadRow] = aR.y;
        As[loadCol + 2][loadRow] = aR.z;
        As[loadCol + 3][loadRow] = aR.w;
        Bs[loadCol + 0][loadRow] = wR.x;
        Bs[loadCol + 1][loadRow] = wR.y;
        Bs[loadCol + 2][loadRow] = wR.z;
        Bs[loadCol + 3][loadRow] = wR.w;
        __syncthreads();

        if (kt < 23) {
            aR = *(const float4*)(Ap + (kt + 1) * 16);
            wR = *(const float4*)(Wp + (kt + 1) * 16);
        }

#pragma unroll
        for (int k = 0; k < 16; ++k) {
            float4 av = *(const float4*)&As[k][ty << 2];
            float4 bv = *(const float4*)&Bs[k][tx << 2];
            float a[4] = {av.x, av.y, av.z, av.w};
            float b[4] = {bv.x, bv.y, bv.z, bv.w};
#pragma unroll
            for (int i = 0; i < 4; i++)
#pragma unroll
                for (int j = 0; j < 4; j++)
                    acc[i][j] = fmaf(a[i], b[j], acc[i][j]);
        }
        __syncthreads();
    }

#pragma unroll
    for (int i = 0; i < 4; i++) {
        const int m = m0 + (ty << 2) + i;
#pragma unroll
        for (int j = 0; j < 4; j++) {
            const int n = n0 + (tx << 2) + j;
            float v = acc[i][j];
            if (doAct) {
                v += bias[n];
                v = fmaxf(v, 0.f) + log1pf(expf(-fabsf(v)));
            }
            Cc[m * 384 + n] = v;
        }
    }
}

// ---------------------------------------------------------------------------
// K3: causal depthwise conv(4) + silu, pack scalar stream g_SC[b][d][l].
// ---------------------------------------------------------------------------
__global__ __launch_bounds__(384) void conv_sc_kernel(
    const float* __restrict__ x,
    const float* __restrict__ convw,
    const float* __restrict__ convb,
    const float* __restrict__ Dvec)
{
    const int d  = threadIdx.x;
    const int b  = blockIdx.y;
    const int l0 = blockIdx.x * 16;

    const float c0 = convw[d * 4 + 0];
    const float c1 = convw[d * 4 + 1];
    const float c2 = convw[d * 4 + 2];
    const float c3 = convw[d * 4 + 3];
    const float cb = convb[d];
    const float Dd = Dvec[d];

    const float* xb  = x    + b * 384 * 384 + d;
    const float* dtp = g_DT + b * 384 * 384 + d;
    float4*      scp = g_SC + (b * 384 + d) * 384;

    float w0 = (l0 - 3 >= 0) ? xb[(l0 - 3) * 384] : 0.f;
    float w1 = (l0 - 2 >= 0) ? xb[(l0 - 2) * 384] : 0.f;
    float w2 = (l0 - 1 >= 0) ? xb[(l0 - 1) * 384] : 0.f;

    for (int i = 0; i < 16; ++i) {
        const int l = l0 + i;
        const float w3 = xb[l * 384];
        float v = fmaf(w0, c0, fmaf(w1, c1, fmaf(w2, c2, fmaf(w3, c3, cb))));
        const float u  = v / (1.f + expf(-v));     // silu
        const float dt = dtp[l * 384];
        scp[l] = make_float4(dt, dt * u, u * Dd, 0.f);
        w0 = w1; w1 = w2; w2 = w3;
    }
}

// ---------------------------------------------------------------------------
// SCAN v3: grid 192 CTAs, 192 threads (6 warps). CTA = 4 channels of batch b.
// ---------------------------------------------------------------------------
#define TL 48   // l-tile between smem reductions (384/48 = 8 tiles)

__global__ __launch_bounds__(192) void scan_kernel(
    const float* __restrict__ A_log,
    float* __restrict__ out)
{
    // part[l_in_tile][warp*8 + subgroup] = float4 of 4 channel partials
    __shared__ float4 part[TL][49];   // 49 pad -> conflict-free reduce

    const int tid  = threadIdx.x;
    const int lane = tid & 31;
    const int wid  = tid >> 5;
    const int s2   = tid;              // float2-state index 0..191

    const int pid = blockIdx.x;        // 0..191
    const int b   = pid / 96;
    const int d0  = (pid - b * 96) * 4;

    // Per-channel invariants: A2 (log2-scaled -exp(A_log)) and Bm row element
    float A2x[4], A2y[4], Bmx[4], Bmy[4], hx[4], hy[4];
    const float4* scp[4];
#pragma unroll
    for (int c = 0; c < 4; ++c) {
        const int d = d0 + c;
        float2 a = ((const float2*)(A_log + d * 384))[s2];
        A2x[c] = -ex2f(a.x * LOG2E) * LOG2E;
        A2y[c] = -ex2f(a.y * LOG2E) * LOG2E;
        float2 bm = ((const float2*)(g_BM + (b * 384 + d) * 384))[s2];
        Bmx[c] = bm.x;  Bmy[c] = bm.y;
        hx[c] = 0.f;    hy[c] = 0.f;
        scp[c] = g_SC + (b * 384 + d) * 384;
    }

    const float2* Cb2 = (const float2*)(g_CM + b * 147456);

    // prefetch l = 0
    float4 sc_n[4];
#pragma unroll
    for (int c = 0; c < 4; ++c) sc_n[c] = __ldg(scp[c]);
    float2 C_n = __ldg(Cb2 + s2);

    float* outB = out + (size_t)b * 147456 + d0;

    for (int tile = 0; tile < 8; ++tile) {
        const int lbase = tile * TL;
#pragma unroll 4
        for (int i = 0; i < TL; ++i) {
            const int l = lbase + i;
            float4 sc[4];
#pragma unroll
            for (int c = 0; c < 4; ++c) sc[c] = sc_n[c];
            const float2 Cv = C_n;

            const int ln = (l < 383) ? (l + 1) : 383;
#pragma unroll
            for (int c = 0; c < 4; ++c) sc_n[c] = __ldg(scp[c] + ln);
            C_n = __ldg(Cb2 + ln * 192 + s2);

            float acc[4];
#pragma unroll
            for (int c = 0; c < 4; ++c) {
                float e0 = ex2f(sc[c].x * A2x[c]);
                hx[c] = fmaf(e0, hx[c], sc[c].y * Bmx[c]);
                float e1 = ex2f(sc[c].x * A2y[c]);
                hy[c] = fmaf(e1, hy[c], sc[c].y * Bmy[c]);
                acc[c] = fmaf(hy[c], Cv.y, hx[c] * Cv.x);
            }
            // 2-level reduce: 32 lanes -> 8 partials (4 independent short chains)
#pragma unroll
            for (int c = 0; c < 4; ++c) {
                acc[c] += __shfl_xor_sync(0xffffffffu, acc[c], 16);
                acc[c] += __shfl_xor_sync(0xffffffffu, acc[c], 8);
            }
            if (lane < 8)
                part[i][wid * 8 + lane] = make_float4(acc[0], acc[1], acc[2], acc[3]);
        }
        __syncthreads();

        // Reduce: threads 0..47 each finish one l (sum 48 float4 partials)
        if (tid < TL) {
            float4 s = part[tid][0];
#pragma unroll 8
            for (int j = 1; j < 48; ++j) {
                float4 p = part[tid][j];
                s.x += p.x; s.y += p.y; s.z += p.z; s.w += p.w;
            }
            const int l = lbase + tid;
            s.x += __ldg(scp[0] + l).z;
            s.y += __ldg(scp[1] + l).z;
            s.z += __ldg(scp[2] + l).z;
            s.w += __ldg(scp[3] + l).z;
            *(float4*)(outB + (size_t)l * 384) = s;
        }
        __syncthreads();
    }
}

// ---------------------------------------------------------------------------
extern "C" void kernel_launch(void* const* d_in, const int* in_sizes, int n_in,
                              void* d_out, int out_size)
{
    const float* x      = (const float*)d_in[0];
    const float* A_log  = (const float*)d_in[1];
    const float* Dvec   = (const float*)d_in[2];
    const float* dt_w   = (const float*)d_in[3];
    const float* dt_b   = (const float*)d_in[4];
    const float* B_w    = (const float*)d_in[5];
    const float* C_w    = (const float*)d_in[6];
    const float* conv_w = (const float*)d_in[7];
    const float* conv_b = (const float*)d_in[8];
    float* out = (float*)d_out;

    gemm_dual<<<dim3(12, 12), 256>>>(x, dt_w, B_w, dt_b, 0);
    conv_sc_kernel<<<dim3(24, 2), 384>>>(x, conv_w, conv_b, Dvec);
    gemm_dual<<<dim3(12, 12), 256>>>(x, B_w, C_w, nullptr, 1);
    scan_kernel<<<192, 192>>>(A_log, out);
}

// round 4
// speedup vs baseline: 1.7419x; 1.2412x over previous
#include <cuda_runtime.h>

// ---------------------------------------------------------------------------
// MambaSSM: B=2, L=384, d_inner=384, d_state=384, dt_rank=384, d_conv=4
//
//   GEMM1 (fused): dt = softplus(x @ dt_w^T + dt_b)   -> g_DT   [768x384]
//                  x_dbl = x @ B_w^T                  -> g_XDBL [768x384]
//   K3:            u = silu(causal_conv(x)+cb); pack per-channel scalar stream
//                  g_SC[b][d][l] = (dt, dt*u, u*D[d], 0)
//   GEMM2 (fused): Bm = x_dbl @ B_w^T                 -> g_BM   [768x384]
//                  Cm = x_dbl @ C_w^T                 -> g_CM   [768x384]
//   SCAN v4: CTA = 2 channels x 192 lanes = 384 threads (12 warps), grid 384.
//     Thread owns ONE float2 of state for ONE channel -> 4608 warps chip-wide.
//     Per step: 2-level shuffle (32->8), lanes<8 store partial; every 48 steps
//     one smem tree-reduce finishes y. C row shared by both channels via L1.
// ---------------------------------------------------------------------------

#define LOG2E 1.4426950408889634f

__device__ float  g_DT  [768 * 384];
__device__ float  g_XDBL[768 * 384];
__device__ float  g_BM  [768 * 384];
__device__ float  g_CM  [768 * 384];
__device__ float4 g_SC  [768 * 384];   // [b][d][l] : (dt, dt*u, u*D, 0)

__device__ __forceinline__ float ex2f(float x) {
    float y;
    asm("ex2.approx.ftz.f32 %0, %1;" : "=f"(y) : "f"(x));
    return y;
}

// ---------------------------------------------------------------------------
// Dual-output tiled SGEMM: C[m,n] = sum_k A[m,k] * W[n,k]
// ---------------------------------------------------------------------------
__global__ __launch_bounds__(256) void gemm_dual(
    const float* __restrict__ A_ext,
    const float* __restrict__ Wa,
    const float* __restrict__ Wb,
    const float* __restrict__ bias,
    int phase)
{
    __shared__ float As[16][64];
    __shared__ float Bs[16][64];

    const float* A  = (phase == 0) ? A_ext : g_XDBL;
    float*       Ca = (phase == 0) ? g_DT  : g_BM;
    float*       Cb = (phase == 0) ? g_XDBL: g_CM;

    const int tid = threadIdx.x;
    const int m0  = blockIdx.x * 64;
    const int bn  = blockIdx.y;            // 0..11
    const bool second = (bn >= 6);
    const float* W  = second ? Wb : Wa;
    float*       Cc = second ? Cb : Ca;
    const bool doAct = (phase == 0) && !second;
    const int n0 = (second ? bn - 6 : bn) * 64;

    const int loadRow = tid >> 2;          // 0..63
    const int loadCol = (tid & 3) << 2;    // 0,4,8,12
    const float* Ap = A + (m0 + loadRow) * 384 + loadCol;
    const float* Wp = W + (n0 + loadRow) * 384 + loadCol;

    float4 aR = *(const float4*)Ap;
    float4 wR = *(const float4*)Wp;

    float acc[4][4];
#pragma unroll
    for (int i = 0; i < 4; i++)
#pragma unroll
        for (int j = 0; j < 4; j++) acc[i][j] = 0.f;

    const int tx = tid & 15;
    const int ty = tid >> 4;

    for (int kt = 0; kt < 24; ++kt) {
        As[loadCol + 0][loadRow] = aR.x;
        As[loadCol + 1][loadRow] = aR.y;
        As[loadCol + 2][loadRow] = aR.z;
        As[loadCol + 3][loadRow] = aR.w;
        Bs[loadCol + 0][loadRow] = wR.x;
        Bs[loadCol + 1][loadRow] = wR.y;
        Bs[loadCol + 2][loadRow] = wR.z;
        Bs[loadCol + 3][loadRow] = wR.w;
        __syncthreads();

        if (kt < 23) {
            aR = *(const float4*)(Ap + (kt + 1) * 16);
            wR = *(const float4*)(Wp + (kt + 1) * 16);
        }

#pragma unroll
        for (int k = 0; k < 16; ++k) {
            float4 av = *(const float4*)&As[k][ty << 2];
            float4 bv = *(const float4*)&Bs[k][tx << 2];
            float a[4] = {av.x, av.y, av.z, av.w};
            float b[4] = {bv.x, bv.y, bv.z, bv.w};
#pragma unroll
            for (int i = 0; i < 4; i++)
#pragma unroll
                for (int j = 0; j < 4; j++)
                    acc[i][j] = fmaf(a[i], b[j], acc[i][j]);
        }
        __syncthreads();
    }

#pragma unroll
    for (int i = 0; i < 4; i++) {
        const int m = m0 + (ty << 2) + i;
#pragma unroll
        for (int j = 0; j < 4; j++) {
            const int n = n0 + (tx << 2) + j;
            float v = acc[i][j];
            if (doAct) {
                v += bias[n];
                v = fmaxf(v, 0.f) + log1pf(expf(-fabsf(v)));
            }
            Cc[m * 384 + n] = v;
        }
    }
}

// ---------------------------------------------------------------------------
// K3: causal depthwise conv(4) + silu, pack scalar stream g_SC[b][d][l].
// ---------------------------------------------------------------------------
__global__ __launch_bounds__(384) void conv_sc_kernel(
    const float* __restrict__ x,
    const float* __restrict__ convw,
    const float* __restrict__ convb,
    const float* __restrict__ Dvec)
{
    const int d  = threadIdx.x;
    const int b  = blockIdx.y;
    const int l0 = blockIdx.x * 16;

    const float c0 = convw[d * 4 + 0];
    const float c1 = convw[d * 4 + 1];
    const float c2 = convw[d * 4 + 2];
    const float c3 = convw[d * 4 + 3];
    const float cb = convb[d];
    const float Dd = Dvec[d];

    const float* xb  = x    + b * 384 * 384 + d;
    const float* dtp = g_DT + b * 384 * 384 + d;
    float4*      scp = g_SC + (b * 384 + d) * 384;

    float w0 = (l0 - 3 >= 0) ? xb[(l0 - 3) * 384] : 0.f;
    float w1 = (l0 - 2 >= 0) ? xb[(l0 - 2) * 384] : 0.f;
    float w2 = (l0 - 1 >= 0) ? xb[(l0 - 1) * 384] : 0.f;

    for (int i = 0; i < 16; ++i) {
        const int l = l0 + i;
        const float w3 = xb[l * 384];
        float v = fmaf(w0, c0, fmaf(w1, c1, fmaf(w2, c2, fmaf(w3, c3, cb))));
        const float u  = v / (1.f + expf(-v));     // silu
        const float dt = dtp[l * 384];
        scp[l] = make_float4(dt, dt * u, u * Dd, 0.f);
        w0 = w1; w1 = w2; w2 = w3;
    }
}

// ---------------------------------------------------------------------------
// SCAN v4: grid 384, block 384 (12 warps). CTA = 2 channels of one batch.
// tid 0..191 -> channel d0 (s2 = tid); tid 192..383 -> channel d0+1.
// ---------------------------------------------------------------------------
#define TL 48   // l-tile between smem reductions (384/48 = 8 tiles)

__global__ __launch_bounds__(384) void scan_kernel(
    const float* __restrict__ A_log,
    float* __restrict__ out)
{
    __shared__ float part[2][TL][49];   // [ch][l_in_tile][48 partials + pad]

    const int tid  = threadIdx.x;
    const int lane = tid & 31;
    const int ch   = tid >= 192;
    const int s2   = tid - ch * 192;        // float2-state index 0..191
    const int wid6 = (tid >> 5) - ch * 6;   // warp index within channel 0..5

    const int pid = blockIdx.x;             // 0..383
    const int b   = pid / 192;
    const int d   = (pid - b * 192) * 2 + ch;

    // Per-thread invariants
    const float2 a = ((const float2*)(A_log + d * 384))[s2];
    const float A2x = -ex2f(a.x * LOG2E) * LOG2E;
    const float A2y = -ex2f(a.y * LOG2E) * LOG2E;
    const float2 bm = ((const float2*)(g_BM + (b * 384 + d) * 384))[s2];
    float hx = 0.f, hy = 0.f;

    const float4* scp = g_SC + (b * 384 + d) * 384;
    const float2* Cb2 = (const float2*)(g_CM + b * 147456);

    // prefetch l = 0
    float4 sc_n = __ldg(scp);
    float2 C_n  = __ldg(Cb2 + s2);

    for (int tile = 0; tile < 8; ++tile) {
        const int lbase = tile * TL;
#pragma unroll 4
        for (int i = 0; i < TL; ++i) {
            const int l = lbase + i;
            const float4 sc = sc_n;
            const float2 Cv = C_n;
            const int ln = (l < 383) ? (l + 1) : 383;
            sc_n = __ldg(scp + ln);
            C_n  = __ldg(Cb2 + ln * 192 + s2);

            const float e0 = ex2f(sc.x * A2x);
            hx = fmaf(e0, hx, sc.y * bm.x);
            const float e1 = ex2f(sc.x * A2y);
            hy = fmaf(e1, hy, sc.y * bm.y);
            float acc = fmaf(hy, Cv.y, hx * Cv.x);

            acc += __shfl_xor_sync(0xffffffffu, acc, 16);
            acc += __shfl_xor_sync(0xffffffffu, acc, 8);
            if (lane < 8)
                part[ch][i][wid6 * 8 + lane] = acc;
        }
        __syncthreads();

        // Final reduce: threads 0..95 -> (c, l): sum 48 partials + u*D term
        if (tid < 2 * TL) {
            const int c  = tid / TL;
            const int li = tid - c * TL;
            const float* p = part[c][li];
            float s0 = 0.f, s1 = 0.f, s2r = 0.f, s3 = 0.f;
#pragma unroll
            for (int j = 0; j < 48; j += 4) {
                s0 += p[j]; s1 += p[j + 1]; s2r += p[j + 2]; s3 += p[j + 3];
            }
            const int l = lbase + li;
            const int dd = (pid - b * 192) * 2 + c;
            float y = (s0 + s1) + (s2r + s3);
            y += __ldg(&((const float4*)(g_SC + (b * 384 + dd) * 384))[l].z);
            out[(size_t)b * 147456 + (size_t)l * 384 + dd] = y;
        }
        __syncthreads();
    }
}

// ---------------------------------------------------------------------------
extern "C" void kernel_launch(void* const* d_in, const int* in_sizes, int n_in,
                              void* d_out, int out_size)
{
    const float* x      = (const float*)d_in[0];
    const float* A_log  = (const float*)d_in[1];
    const float* Dvec   = (const float*)d_in[2];
    const float* dt_w   = (const float*)d_in[3];
    const float* dt_b   = (const float*)d_in[4];
    const float* B_w    = (const float*)d_in[5];
    const float* C_w    = (const float*)d_in[6];
    const float* conv_w = (const float*)d_in[7];
    const float* conv_b = (const float*)d_in[8];
    float* out = (float*)d_out;

    gemm_dual<<<dim3(12, 12), 256>>>(x, dt_w, B_w, dt_b, 0);
    conv_sc_kernel<<<dim3(24, 2), 384>>>(x, conv_w, conv_b, Dvec);
    gemm_dual<<<dim3(12, 12), 256>>>(x, B_w, C_w, nullptr, 1);
    scan_kernel<<<384, 384>>>(A_log, out);
}

// round 5
// speedup vs baseline: 1.9488x; 1.1188x over previous
#include <cuda_runtime.h>

// ---------------------------------------------------------------------------
// MambaSSM: B=2, L=384, d_inner=384, d_state=384, dt_rank=384, d_conv=4
//
//   GEMM1 (fused): dt = softplus(x @ dt_w^T + dt_b)   -> g_DT   [768x384]
//                  x_dbl = x @ B_w^T                  -> g_XDBL [768x384]
//   K3:            u = silu(causal_conv(x)+cb); pack per-channel scalar stream
//                  g_SC[b][d][l] = (dt, dt*u, u*D[d], 0)
//   GEMM2 (fused): Bm = x_dbl @ B_w^T                 -> g_BM   [768x384]
//                  Cm = x_dbl @ C_w^T                 -> g_CM   [768x384]
//   SCAN v5: CTA = 2 channels x 192 float2-lanes = 384 threads, grid 384.
//     - sc stream staged in smem (double-buffered per 48-tile), loaded by
//       spare threads during the reduce phase (no per-iter LDG broadcast).
//     - C prefetched 2 iterations ahead (covers L2-hit latency).
//     - reduction deferred one iteration (SHFL chain off critical path).
// ---------------------------------------------------------------------------

#define LOG2E 1.4426950408889634f

__device__ float  g_DT  [768 * 384];
__device__ float  g_XDBL[768 * 384];
__device__ float  g_BM  [768 * 384];
__device__ float  g_CM  [768 * 384];
__device__ float4 g_SC  [768 * 384];   // [b][d][l] : (dt, dt*u, u*D, 0)

__device__ __forceinline__ float ex2f(float x) {
    float y;
    asm("ex2.approx.ftz.f32 %0, %1;" : "=f"(y) : "f"(x));
    return y;
}

// ---------------------------------------------------------------------------
// Dual-output tiled SGEMM: C[m,n] = sum_k A[m,k] * W[n,k]
// ---------------------------------------------------------------------------
__global__ __launch_bounds__(256) void gemm_dual(
    const float* __restrict__ A_ext,
    const float* __restrict__ Wa,
    const float* __restrict__ Wb,
    const float* __restrict__ bias,
    int phase)
{
    __shared__ float As[16][64];
    __shared__ float Bs[16][64];

    const float* A  = (phase == 0) ? A_ext : g_XDBL;
    float*       Ca = (phase == 0) ? g_DT  : g_BM;
    float*       Cb = (phase == 0) ? g_XDBL: g_CM;

    const int tid = threadIdx.x;
    const int m0  = blockIdx.x * 64;
    const int bn  = blockIdx.y;            // 0..11
    const bool second = (bn >= 6);
    const float* W  = second ? Wb : Wa;
    float*       Cc = second ? Cb : Ca;
    const bool doAct = (phase == 0) && !second;
    const int n0 = (second ? bn - 6 : bn) * 64;

    const int loadRow = tid >> 2;          // 0..63
    const int loadCol = (tid & 3) << 2;    // 0,4,8,12
    const float* Ap = A + (m0 + loadRow) * 384 + loadCol;
    const float* Wp = W + (n0 + loadRow) * 384 + loadCol;

    float4 aR = *(const float4*)Ap;
    float4 wR = *(const float4*)Wp;

    float acc[4][4];
#pragma unroll
    for (int i = 0; i < 4; i++)
#pragma unroll
        for (int j = 0; j < 4; j++) acc[i][j] = 0.f;

    const int tx = tid & 15;
    const int ty = tid >> 4;

    for (int kt = 0; kt < 24; ++kt) {
        As[loadCol + 0][loadRow] = aR.x;
        As[loadCol + 1][loadRow] = aR.y;
        As[loadCol + 2][loadRow] = aR.z;
        As[loadCol + 3][loadRow] = aR.w;
        Bs[loadCol + 0][loadRow] = wR.x;
        Bs[loadCol + 1][loadRow] = wR.y;
        Bs[loadCol + 2][loadRow] = wR.z;
        Bs[loadCol + 3][loadRow] = wR.w;
        __syncthreads();

        if (kt < 23) {
            aR = *(const float4*)(Ap + (kt + 1) * 16);
            wR = *(const float4*)(Wp + (kt + 1) * 16);
        }

#pragma unroll
        for (int k = 0; k < 16; ++k) {
            float4 av = *(const float4*)&As[k][ty << 2];
            float4 bv = *(const float4*)&Bs[k][tx << 2];
            float a[4] = {av.x, av.y, av.z, av.w};
            float b[4] = {bv.x, bv.y, bv.z, bv.w};
#pragma unroll
            for (int i = 0; i < 4; i++)
#pragma unroll
                for (int j = 0; j < 4; j++)
                    acc[i][j] = fmaf(a[i], b[j], acc[i][j]);
        }
        __syncthreads();
    }

#pragma unroll
    for (int i = 0; i < 4; i++) {
        const int m = m0 + (ty << 2) + i;
#pragma unroll
        for (int j = 0; j < 4; j++) {
            const int n = n0 + (tx << 2) + j;
            float v = acc[i][j];
            if (doAct) {
                v += bias[n];
                v = fmaxf(v, 0.f) + log1pf(expf(-fabsf(v)));
            }
            Cc[m * 384 + n] = v;
        }
    }
}

// ---------------------------------------------------------------------------
// K3: causal depthwise conv(4) + silu, pack scalar stream g_SC[b][d][l].
// ---------------------------------------------------------------------------
__global__ __launch_bounds__(384) void conv_sc_kernel(
    const float* __restrict__ x,
    const float* __restrict__ convw,
    const float* __restrict__ convb,
    const float* __restrict__ Dvec)
{
    const int d  = threadIdx.x;
    const int b  = blockIdx.y;
    const int l0 = blockIdx.x * 16;

    const float c0 = convw[d * 4 + 0];
    const float c1 = convw[d * 4 + 1];
    const float c2 = convw[d * 4 + 2];
    const float c3 = convw[d * 4 + 3];
    const float cb = convb[d];
    const float Dd = Dvec[d];

    const float* xb  = x    + b * 384 * 384 + d;
    const float* dtp = g_DT + b * 384 * 384 + d;
    float4*      scp = g_SC + (b * 384 + d) * 384;

    float w0 = (l0 - 3 >= 0) ? xb[(l0 - 3) * 384] : 0.f;
    float w1 = (l0 - 2 >= 0) ? xb[(l0 - 2) * 384] : 0.f;
    float w2 = (l0 - 1 >= 0) ? xb[(l0 - 1) * 384] : 0.f;

    for (int i = 0; i < 16; ++i) {
        const int l = l0 + i;
        const float w3 = xb[l * 384];
        float v = fmaf(w0, c0, fmaf(w1, c1, fmaf(w2, c2, fmaf(w3, c3, cb))));
        const float u  = v / (1.f + expf(-v));     // silu
        const float dt = dtp[l * 384];
        scp[l] = make_float4(dt, dt * u, u * Dd, 0.f);
        w0 = w1; w1 = w2; w2 = w3;
    }
}

// ---------------------------------------------------------------------------
// SCAN v5: grid 384, block 384 (12 warps). CTA = 2 channels of one batch.
// tid 0..191 -> channel d0 (s2 = tid); tid 192..383 -> channel d0+1.
// ---------------------------------------------------------------------------
#define TL 48   // l-tile between smem reductions (384/48 = 8 tiles)

__global__ __launch_bounds__(384) void scan_kernel(
    const float* __restrict__ A_log,
    float* __restrict__ out)
{
    __shared__ float  part[2][TL][49];     // [ch][l_in_tile][48 partials + pad]
    __shared__ float4 scbuf[2][2][TL];     // [buf][ch][l_in_tile]

    const int tid  = threadIdx.x;
    const int lane = tid & 31;
    const int ch   = tid >= 192;
    const int s2   = tid - ch * 192;        // float2-state index 0..191
    const int wid6 = (tid >> 5) - ch * 6;   // warp index within channel 0..5

    const int pid   = blockIdx.x;           // 0..383
    const int b     = pid / 192;
    const int dbase = (pid - b * 192) * 2;
    const int d     = dbase + ch;

    // Per-thread invariants
    const float2 a = ((const float2*)(A_log + d * 384))[s2];
    const float A2x = -ex2f(a.x * LOG2E) * LOG2E;
    const float A2y = -ex2f(a.y * LOG2E) * LOG2E;
    const float2 bm = ((const float2*)(g_BM + (b * 384 + d) * 384))[s2];
    float hx = 0.f, hy = 0.f;

    const float4* scp0 = g_SC + (b * 384 + dbase) * 384;   // channel 0 stream
    const float2* Cb2  = (const float2*)(g_CM + b * 147456) + s2;

    // Preload tile 0 sc (threads 0..95: c = tid/48, li = tid%48)
    if (tid < 96) {
        const int c = tid / TL, li = tid - c * TL;
        scbuf[0][c][li] = __ldg(scp0 + c * 384 + li);
    }
    // Prefetch C rows l=0,1
    float2 C0 = __ldg(Cb2);
    float2 C1 = __ldg(Cb2 + 192);
    __syncthreads();

    float accP = 0.f;

    for (int tile = 0; tile < 8; ++tile) {
        const int lbase = tile * TL;
        const int buf   = tile & 1;

#pragma unroll 6
        for (int i = 0; i < TL; ++i) {
            const int l = lbase + i;
            const float4 sc = scbuf[buf][ch][i];   // LDS broadcast
            const float2 Cv = C0;
            C0 = C1;
            const int lpf = (l + 2 < 384) ? (l + 2) : 383;
            C1 = __ldg(Cb2 + lpf * 192);

            const float e0 = ex2f(sc.x * A2x);
            hx = fmaf(e0, hx, sc.y * bm.x);
            const float e1 = ex2f(sc.x * A2y);
            hy = fmaf(e1, hy, sc.y * bm.y);
            const float acc = fmaf(hy, Cv.y, hx * Cv.x);

            if (i > 0) {   // deferred: reduce previous iteration's partial
                accP += __shfl_xor_sync(0xffffffffu, accP, 16);
                accP += __shfl_xor_sync(0xffffffffu, accP, 8);
                if (lane < 8) part[ch][i - 1][wid6 * 8 + lane] = accP;
            }
            accP = acc;
        }
        // flush last iteration of the tile
        accP += __shfl_xor_sync(0xffffffffu, accP, 16);
        accP += __shfl_xor_sync(0xffffffffu, accP, 8);
        if (lane < 8) part[ch][TL - 1][wid6 * 8 + lane] = accP;
        __syncthreads();

        // Reduce + write out (tid<96); load next tile's sc (tid 96..191)
        if (tid < 96) {
            const int c  = tid / TL;
            const int li = tid - c * TL;
            const float* p = part[c][li];
            float t0 = 0.f, t1 = 0.f, t2 = 0.f, t3 = 0.f;
#pragma unroll
            for (int j = 0; j < 48; j += 4) {
                t0 += p[j]; t1 += p[j + 1]; t2 += p[j + 2]; t3 += p[j + 3];
            }
            const int l = lbase + li;
            float y = (t0 + t1) + (t2 + t3);
            y += scbuf[buf][c][li].z;              // u*D term
            out[(size_t)b * 147456 + (size_t)l * 384 + dbase + c] = y;
        } else if (tid < 192 && tile < 7) {
            const int t2i = tid - 96;
            const int c = t2i / TL, li = t2i - c * TL;
            scbuf[buf ^ 1][c][li] = __ldg(scp0 + c * 384 + lbase + TL + li);
        }
        __syncthreads();
    }
}

// ---------------------------------------------------------------------------
extern "C" void kernel_launch(void* const* d_in, const int* in_sizes, int n_in,
                              void* d_out, int out_size)
{
    const float* x      = (const float*)d_in[0];
    const float* A_log  = (const float*)d_in[1];
    const float* Dvec   = (const float*)d_in[2];
    const float* dt_w   = (const float*)d_in[3];
    const float* dt_b   = (const float*)d_in[4];
    const float* B_w    = (const float*)d_in[5];
    const float* C_w    = (const float*)d_in[6];
    const float* conv_w = (const float*)d_in[7];
    const float* conv_b = (const float*)d_in[8];
    float* out = (float*)d_out;

    gemm_dual<<<dim3(12, 12), 256>>>(x, dt_w, B_w, dt_b, 0);
    conv_sc_kernel<<<dim3(24, 2), 384>>>(x, conv_w, conv_b, Dvec);
    gemm_dual<<<dim3(12, 12), 256>>>(x, B_w, C_w, nullptr, 1);
    scan_kernel<<<384, 384>>>(A_log, out);
}